// round 8
// baseline (speedup 1.0000x reference)
#include <cuda_runtime.h>
#include <cstdint>

#define FULLMASK 0xFFFFFFFFu
typedef unsigned long long u64;

static constexpr int NB      = 131072;
static constexpr int NO      = 128;
static constexpr int NF      = 32;
static constexpr int WPB     = 4;
static constexpr int THREADS = WPB * 32;            // 128
static constexpr int NBLOCKS = 4096;
static constexpr int TOTAL_WARPS = NBLOCKS * WPB;   // 16384
static constexpr int ITERS   = NB / (TOTAL_WARPS * 2);  // 4 (2 samples/warp/iter)

// ---- f32x2 packed helpers; carrier is u64 ("l" binds 64-bit int regs) --------
__device__ __forceinline__ u64 pack2(float lo, float hi) {
    u64 r;
    asm("mov.b64 %0, {%1,%2};" : "=l"(r) : "f"(lo), "f"(hi));
    return r;
}
__device__ __forceinline__ void unpack2(u64 a, float& lo, float& hi) {
    asm("mov.b64 {%0,%1}, %2;" : "=f"(lo), "=f"(hi) : "l"(a));
}
__device__ __forceinline__ u64 ffma2(u64 a, u64 b, u64 c) {
    u64 r;
    asm("fma.rn.f32x2 %0, %1, %2, %3;" : "=l"(r) : "l"(a), "l"(b), "l"(c));
    return r;
}

__global__ __launch_bounds__(THREADS, 5)
void slater_det_kernel(const int4* __restrict__ nvec,
                       const float* __restrict__ Phi,
                       float* __restrict__ out)
{
    __shared__ float PhiT[NO * 33];       // PhiT[o*33+i] = Phi[i*128+o]
    __shared__ int   idxs[WPB][2][NF];
    // pivot-row broadcast: [wid][k-parity][j=16B chunk][half]; halves on
    // disjoint banks (adjacent 16B), double-buffered by k parity.
    __shared__ ulonglong2 prow[WPB][2][8][2];

    const int tid = threadIdx.x;
    for (int l = tid; l < NO * NF; l += THREADS) {
        const int o = l >> 5;
        const int i = l & 31;
        PhiT[o * 33 + i] = Phi[i * NO + o];
    }
    __syncthreads();

    const int wid  = tid >> 5;
    const int lane = tid & 31;
    const int h    = lane >> 4;     // half-warp = which of 2 samples
    const int t    = lane & 15;     // sublane; owns rows t and t+16
    const unsigned hm = 0xFFFFu << (h << 4);   // half-warp membermask
    int* mi = idxs[wid][h];
    const int gw = blockIdx.x * WPB + wid;

    for (int it = 0; it < ITERS; ++it) {
        const int s = 2 * (gw + it * TOTAL_WARPS) + h;

        // ---- occupied-orbital extraction (ascending), per half-warp ---------
        const int4 va = nvec[s * 32 + 2 * t + 0];
        const int4 vb = nvec[s * 32 + 2 * t + 1];
        const int c = (va.x != 0) + (va.y != 0) + (va.z != 0) + (va.w != 0)
                    + (vb.x != 0) + (vb.y != 0) + (vb.z != 0) + (vb.w != 0);
        int pref = c;
        #pragma unroll
        for (int d = 1; d < 16; d <<= 1) {
            const int u = __shfl_up_sync(FULLMASK, pref, d);
            if (t >= d) pref += u;
        }
        int pos = pref - c;
        __syncwarp();
        const int base = 8 * t;
        if (va.x) mi[pos++] = base + 0;
        if (va.y) mi[pos++] = base + 1;
        if (va.z) mi[pos++] = base + 2;
        if (va.w) mi[pos++] = base + 3;
        if (vb.x) mi[pos++] = base + 4;
        if (vb.y) mi[pos++] = base + 5;
        if (vb.z) mi[pos++] = base + 6;
        if (vb.w) mi[pos++] = base + 7;
        __syncwarp();

        // ---- gather: A0 = row t, A1 = row t+16; cols packed in pairs --------
        u64 A0[16], A1[16];
        #pragma unroll
        for (int q = 0; q < 16; ++q) {
            const int o0 = mi[2 * q + 0];
            const int o1 = mi[2 * q + 1];
            A0[q] = pack2(PhiT[o0 * 33 + t],      PhiT[o1 * 33 + t]);
            A1[q] = pack2(PhiT[o0 * 33 + t + 16], PhiT[o1 * 33 + t + 16]);
        }

        // ---- LU, partial pivoting, virtual rows, smem pivot-row broadcast ---
        float det = 1.0f;
        int vr0 = t, vr1 = t + 16;
        unsigned m0 = ~0u, m1 = ~0u;        // life masks (~0 = row active)
        #pragma unroll
        for (int k = 0; k < 32; ++k) {
            float l0, h0, l1, h1;
            unpack2(A0[k >> 1], l0, h0);
            unpack2(A1[k >> 1], l1, h1);
            const float ak0 = (k & 1) ? h0 : l0;
            const float ak1 = (k & 1) ? h1 : l1;

            const unsigned key0 = __float_as_uint(ak0) & 0x7FFFFFFFu & m0;
            const unsigned key1 = __float_as_uint(ak1) & 0x7FFFFFFFu & m1;
            const bool sl = key1 > key0;
            const unsigned kmax = sl ? key1 : key0;

            // per-half max; mx == |pivot| exactly -> rcp starts immediately
            const unsigned mx = __reduce_max_sync(hm, kmax);
            float inv;
            asm("rcp.approx.f32 %0, %1;" : "=f"(inv) : "f"(__uint_as_float(mx)));
            inv = (mx != 0u) ? inv : 0.f;   // singular -> det 0 path

            const unsigned cand = __ballot_sync(FULLMASK, kmax == mx) & hm;
            const int p = __ffs(cand) - 1;                       // pivot lane
            const unsigned negs = __ballot_sync(FULLMASK, (sl ? ak1 : ak0) < 0.f);
            const unsigned pneg = (negs >> p) & 1u;              // pivot sign

            int rsel = ((sl ? vr1 : vr0) << 1) | (int)sl;
            rsel = __shfl_sync(FULLMASK, rsel, p);
            const int  r    = rsel >> 1;    // pivot's virtual row
            const bool psel = rsel & 1;     // pivot used its row1?

            if (vr0 == k) vr0 = r; else if (vr1 == k) vr1 = r;
            const bool isp = (lane == p);
            if (isp) {
                if (psel) { vr1 = k; m1 = 0u; }
                else      { vr0 = k; m0 = 0u; }
            }

            det *= __uint_as_float(mx ^ ((pneg ^ (unsigned)(r != k)) << 31));

            // f = -ak/pv = (ak*inv) with sign (pneg ? + : -), masked by life
            const unsigned fs = pneg ? 0u : 0x80000000u;
            const float nf0f = __uint_as_float((__float_as_uint(ak0 * inv) & m0) ^ fs);
            const float nf1f = __uint_as_float((__float_as_uint(ak1 * inv) & m1) ^ fs);
            const u64 nf0 = pack2(nf0f, nf0f);
            const u64 nf1 = pack2(nf1f, nf1f);

            if (k < 31) {
                const int jq = k >> 2;      // first 16B chunk (cols 4*jq..)
                // pivot lane stores its row chunk; 2 active lanes, disjoint banks
                if (isp) {
                    if (psel) {
                        #pragma unroll
                        for (int j = jq; j < 8; ++j)
                            prow[wid][k & 1][j][h] = make_ulonglong2(A1[2 * j], A1[2 * j + 1]);
                    } else {
                        #pragma unroll
                        for (int j = jq; j < 8; ++j)
                            prow[wid][k & 1][j][h] = make_ulonglong2(A0[2 * j], A0[2 * j + 1]);
                    }
                }
                __syncwarp();
                #pragma unroll
                for (int j = jq; j < 8; ++j) {
                    const ulonglong2 b = prow[wid][k & 1][j][h];   // broadcast
                    A0[2 * j]     = ffma2(b.x, nf0, A0[2 * j]);
                    A0[2 * j + 1] = ffma2(b.y, nf0, A0[2 * j + 1]);
                    A1[2 * j]     = ffma2(b.x, nf1, A1[2 * j]);
                    A1[2 * j + 1] = ffma2(b.y, nf1, A1[2 * j + 1]);
                }
            }
        }

        if (t == 0) out[s] = det;
    }
}

extern "C" void kernel_launch(void* const* d_in, const int* in_sizes, int n_in,
                              void* d_out, int out_size)
{
    const int4*  nvec = (const int4*)d_in[0];   // n: [131072, 128] int32
    const float* Phi  = (const float*)d_in[1];  // Phi: [32, 128] fp32
    float* out = (float*)d_out;                 // [131072] fp32
    slater_det_kernel<<<NBLOCKS, THREADS>>>(nvec, Phi, out);
}

// round 9
// speedup vs baseline: 1.2210x; 1.2210x over previous
#include <cuda_runtime.h>
#include <cstdint>

#define FULLMASK 0xFFFFFFFFu
typedef unsigned long long u64;

static constexpr int NB      = 131072;
static constexpr int NO      = 128;
static constexpr int NF      = 32;
static constexpr int WPB     = 4;
static constexpr int THREADS = WPB * 32;            // 128
static constexpr int NBLOCKS = 4096;
static constexpr int TOTAL_WARPS = NBLOCKS * WPB;   // 16384
static constexpr int ITERS   = NB / (TOTAL_WARPS * 2);  // 4 (2 samples/warp/iter)

// ---- f32x2 packed helpers; carrier is u64 ("l" binds 64-bit int regs) --------
__device__ __forceinline__ u64 pack2(float lo, float hi) {
    u64 r;
    asm("mov.b64 %0, {%1,%2};" : "=l"(r) : "f"(lo), "f"(hi));
    return r;
}
__device__ __forceinline__ void unpack2(u64 a, float& lo, float& hi) {
    asm("mov.b64 {%0,%1}, %2;" : "=f"(lo), "=f"(hi) : "l"(a));
}
__device__ __forceinline__ u64 ffma2(u64 a, u64 b, u64 c) {
    u64 r;
    asm("fma.rn.f32x2 %0, %1, %2, %3;" : "=l"(r) : "l"(a), "l"(b), "l"(c));
    return r;
}

__global__ __launch_bounds__(THREADS, 5)
void slater_det_kernel(const int4* __restrict__ nvec,
                       const float* __restrict__ Phi,
                       float* __restrict__ out)
{
    __shared__ float PhiT[NO * 33];       // PhiT[o*33+i] = Phi[i*128+o]
    __shared__ int   idxs[WPB][2][NF];

    const int tid = threadIdx.x;
    for (int l = tid; l < NO * NF; l += THREADS) {
        const int o = l >> 5;
        const int i = l & 31;
        PhiT[o * 33 + i] = Phi[i * NO + o];
    }
    __syncthreads();

    const int wid  = tid >> 5;
    const int lane = tid & 31;
    const int h    = lane >> 4;     // half-warp = which of 2 samples
    const int t    = lane & 15;     // sublane; owns rows t and t+16
    const unsigned hm = 0xFFFFu << (h << 4);   // half-warp membermask
    int* mi = idxs[wid][h];
    const int gw = blockIdx.x * WPB + wid;

    for (int it = 0; it < ITERS; ++it) {
        const int s = 2 * (gw + it * TOTAL_WARPS) + h;

        // ---- occupied-orbital extraction (ascending), per half-warp ---------
        const int4 va = nvec[s * 32 + 2 * t + 0];
        const int4 vb = nvec[s * 32 + 2 * t + 1];
        const int c = (va.x != 0) + (va.y != 0) + (va.z != 0) + (va.w != 0)
                    + (vb.x != 0) + (vb.y != 0) + (vb.z != 0) + (vb.w != 0);
        int pref = c;
        #pragma unroll
        for (int d = 1; d < 16; d <<= 1) {
            const int u = __shfl_up_sync(FULLMASK, pref, d);
            if (t >= d) pref += u;
        }
        int pos = pref - c;
        __syncwarp();
        const int base = 8 * t;
        if (va.x) mi[pos++] = base + 0;
        if (va.y) mi[pos++] = base + 1;
        if (va.z) mi[pos++] = base + 2;
        if (va.w) mi[pos++] = base + 3;
        if (vb.x) mi[pos++] = base + 4;
        if (vb.y) mi[pos++] = base + 5;
        if (vb.z) mi[pos++] = base + 6;
        if (vb.w) mi[pos++] = base + 7;
        __syncwarp();

        // ---- gather: A0 = row t, A1 = row t+16; cols packed in pairs --------
        u64 A0[16], A1[16];
        #pragma unroll
        for (int q = 0; q < 16; ++q) {
            const int o0 = mi[2 * q + 0];
            const int o1 = mi[2 * q + 1];
            A0[q] = pack2(PhiT[o0 * 33 + t],      PhiT[o1 * 33 + t]);
            A1[q] = pack2(PhiT[o0 * 33 + t + 16], PhiT[o1 * 33 + t + 16]);
        }

        // ---- LU, partial pivoting, virtual rows, REDUX pivot + shfl bcast ---
        float det = 1.0f;
        int vr0 = t, vr1 = t + 16;
        unsigned m0 = ~0u, m1 = ~0u;        // life masks (~0 = row active)
        #pragma unroll
        for (int k = 0; k < 32; ++k) {
            float l0, h0, l1, h1;
            unpack2(A0[k >> 1], l0, h0);
            unpack2(A1[k >> 1], l1, h1);
            const float ak0 = (k & 1) ? h0 : l0;
            const float ak1 = (k & 1) ? h1 : l1;

            const unsigned key0 = __float_as_uint(ak0) & 0x7FFFFFFFu & m0;
            const unsigned key1 = __float_as_uint(ak1) & 0x7FFFFFFFu & m1;
            const bool sl = key1 > key0;
            const unsigned kmax  = sl ? key1 : key0;
            const float    pcand = sl ? ak1 : ak0;

            // sign ballot issued BEFORE the reduction (independent MIO op)
            const unsigned negs = __ballot_sync(FULLMASK, pcand < 0.f);

            // per-half argmax: low 5 bits carry lane (2^-18 magnitude fuzz)
            const unsigned pk = (kmax & 0xFFFFFFE0u) | (unsigned)lane;
            const unsigned mx = __reduce_max_sync(hm, pk);
            const int p = (int)(mx & 31u);                // pivot lane

            // approximate 1/|pv| from the fuzzed max -> nf ready immediately
            const unsigned mxv = mx & 0xFFFFFFE0u;
            float inv;
            asm("rcp.approx.f32 %0, %1;" : "=f"(inv) : "f"(__uint_as_float(mxv)));
            inv = (mxv != 0u) ? inv : 0.f;                // singular -> det 0
            const unsigned pneg = (negs >> p) & 1u;       // sign(pv)

            // exact pivot value + pivot's virtual row (latency-tolerant uses)
            const float pv = __shfl_sync(FULLMASK, pcand, p);
            int rsel = ((sl ? vr1 : vr0) << 1) | (int)sl;
            rsel = __shfl_sync(FULLMASK, rsel, p);
            const int  r    = rsel >> 1;
            const bool psel = rsel & 1;

            if (vr0 == k) vr0 = r; else if (vr1 == k) vr1 = r;
            if (lane == p) {
                if (psel) { vr1 = k; m1 = 0u; }
                else      { vr0 = k; m0 = 0u; }
            }

            det *= (r != k) ? -pv : pv;                   // exact pv for det

            // nf = -ak/pv = (ak*inv), sign flipped iff pv > 0; life-masked
            const unsigned fs = pneg ? 0u : 0x80000000u;
            const float nf0f = __uint_as_float((__float_as_uint(ak0 * inv) & m0) ^ fs);
            const float nf1f = __uint_as_float((__float_as_uint(ak1 * inv) & m1) ^ fs);
            const u64 nf0 = pack2(nf0f, nf0f);
            const u64 nf1 = pack2(nf1f, nf1f);

            if (k < 31) {
                const int q4 = k >> 1;
                #pragma unroll
                for (int q = q4; q < 16; ++q) {
                    // local sl == psel on the source lane p
                    const u64 tq = sl ? A1[q] : A0[q];
                    const u64 b  = __shfl_sync(FULLMASK, tq, p);  // 2x SHFL.32
                    A0[q] = ffma2(b, nf0, A0[q]);
                    A1[q] = ffma2(b, nf1, A1[q]);
                }
            }
        }

        if (t == 0) out[s] = det;
    }
}

extern "C" void kernel_launch(void* const* d_in, const int* in_sizes, int n_in,
                              void* d_out, int out_size)
{
    const int4*  nvec = (const int4*)d_in[0];   // n: [131072, 128] int32
    const float* Phi  = (const float*)d_in[1];  // Phi: [32, 128] fp32
    float* out = (float*)d_out;                 // [131072] fp32
    slater_det_kernel<<<NBLOCKS, THREADS>>>(nvec, Phi, out);
}

// round 10
// speedup vs baseline: 1.5313x; 1.2542x over previous
#include <cuda_runtime.h>
#include <cstdint>

#define FULLMASK 0xFFFFFFFFu
typedef unsigned long long u64;

static constexpr int NB      = 131072;
static constexpr int NO      = 128;
static constexpr int NF      = 32;
static constexpr int WPB     = 4;
static constexpr int THREADS = WPB * 32;            // 128
static constexpr int NBLOCKS = 4096;
static constexpr int TOTAL_WARPS = NBLOCKS * WPB;   // 16384
static constexpr int ITERS   = NB / (TOTAL_WARPS * 2);  // 4 (2 samples/warp/iter)

// ---- f32x2 packed helpers; carrier is u64 ("l" binds 64-bit int regs) --------
__device__ __forceinline__ u64 pack2(float lo, float hi) {
    u64 r;
    asm("mov.b64 %0, {%1,%2};" : "=l"(r) : "f"(lo), "f"(hi));
    return r;
}
__device__ __forceinline__ void unpack2(u64 a, float& lo, float& hi) {
    asm("mov.b64 {%0,%1}, %2;" : "=f"(lo), "=f"(hi) : "l"(a));
}
__device__ __forceinline__ u64 ffma2(u64 a, u64 b, u64 c) {
    u64 r;
    asm("fma.rn.f32x2 %0, %1, %2, %3;" : "=l"(r) : "l"(a), "l"(b), "l"(c));
    return r;
}

__global__ __launch_bounds__(THREADS, 5)
void slater_det_kernel(const int4* __restrict__ nvec,
                       const float* __restrict__ Phi,
                       float* __restrict__ out)
{
    __shared__ float PhiT[NO * 33];       // PhiT[o*33+i] = Phi[i*128+o]
    __shared__ int   idxs[WPB][2][NF];

    const int tid = threadIdx.x;
    for (int l = tid; l < NO * NF; l += THREADS) {
        const int o = l >> 5;
        const int i = l & 31;
        PhiT[o * 33 + i] = Phi[i * NO + o];
    }
    __syncthreads();

    const int wid  = tid >> 5;
    const int lane = tid & 31;
    const int h    = lane >> 4;     // half-warp = which of 2 samples
    const int t    = lane & 15;     // sublane; owns rows t and t+16
    const unsigned hm = 0xFFFFu << (h << 4);   // half-warp membermask
    int* mi = idxs[wid][h];
    const int gw = blockIdx.x * WPB + wid;

    for (int it = 0; it < ITERS; ++it) {
        const int s = 2 * (gw + it * TOTAL_WARPS) + h;

        // ---- occupied-orbital extraction (ascending), per half-warp ---------
        const int4 va = nvec[s * 32 + 2 * t + 0];
        const int4 vb = nvec[s * 32 + 2 * t + 1];
        const int c = (va.x != 0) + (va.y != 0) + (va.z != 0) + (va.w != 0)
                    + (vb.x != 0) + (vb.y != 0) + (vb.z != 0) + (vb.w != 0);
        int pref = c;
        #pragma unroll
        for (int d = 1; d < 16; d <<= 1) {
            const int u = __shfl_up_sync(FULLMASK, pref, d);
            if (t >= d) pref += u;
        }
        int pos = pref - c;
        __syncwarp();
        const int base = 8 * t;
        if (va.x) mi[pos++] = base + 0;
        if (va.y) mi[pos++] = base + 1;
        if (va.z) mi[pos++] = base + 2;
        if (va.w) mi[pos++] = base + 3;
        if (vb.x) mi[pos++] = base + 4;
        if (vb.y) mi[pos++] = base + 5;
        if (vb.z) mi[pos++] = base + 6;
        if (vb.w) mi[pos++] = base + 7;
        __syncwarp();

        // ---- gather: A0 = row t, A1 = row t+16; cols packed in pairs --------
        u64 A0[16], A1[16];
        #pragma unroll
        for (int q = 0; q < 16; ++q) {
            const int o0 = mi[2 * q + 0];
            const int o1 = mi[2 * q + 1];
            A0[q] = pack2(PhiT[o0 * 33 + t],      PhiT[o1 * 33 + t]);
            A1[q] = pack2(PhiT[o0 * 33 + t + 16], PhiT[o1 * 33 + t + 16]);
        }

        // ---- LU, partial pivoting: butterfly argmax + shfl row broadcast ----
        // No virtual rows: life masks gate eligibility/updates; det magnitude
        // accumulates locally on pivot lanes; sign = permutation parity at end.
        float det_local = 1.0f;
        unsigned m0 = ~0u, m1 = ~0u;        // life masks (~0 = row active)
        int ka = 0, kb = 0;                 // step at which row t / t+16 pivoted
        #pragma unroll
        for (int k = 0; k < 32; ++k) {
            float l0, h0, l1, h1;
            unpack2(A0[k >> 1], l0, h0);
            unpack2(A1[k >> 1], l1, h1);
            const float ak0 = (k & 1) ? h0 : l0;
            const float ak1 = (k & 1) ? h1 : l1;

            const unsigned key0 = __float_as_uint(ak0) & 0x7FFFFFFFu & m0;
            const unsigned key1 = __float_as_uint(ak1) & 0x7FFFFFFFu & m1;
            const bool sl = key1 > key0;
            const unsigned kmax  = sl ? key1 : key0;
            const float    pcand = sl ? ak1 : ak0;

            // argmax key: [magnitude(fuzz 2^-17) | signbit | lane]
            const unsigned sgn = __float_as_uint(pcand) >> 31;
            unsigned pk = (kmax & 0xFFFFFFC0u) | (sgn << 5) | (unsigned)lane;
            #pragma unroll
            for (int d = 1; d < 16; d <<= 1)
                pk = max(pk, __shfl_xor_sync(FULLMASK, pk, d));
            const int p = (int)(pk & 31u);            // pivot lane (this half)
            const unsigned pneg = (pk >> 5) & 1u;     // pivot sign
            const unsigned mxv  = pk & 0xFFFFFFC0u;   // |pivot| (fuzzed)

            float inv;
            asm("rcp.approx.f32 %0, %1;" : "=f"(inv) : "f"(__uint_as_float(mxv)));
            inv = (mxv != 0u) ? inv : 0.f;            // singular -> det 0 path

            if (lane == p) {
                if (sl) { m1 = 0u; kb = k; }
                else    { m0 = 0u; ka = k; }
                det_local *= pcand;                   // exact pivot value
            }

            // nf = -ak/pv = (ak*|1/pv|), sign flipped iff pv > 0; life-masked
            const unsigned fs = pneg ? 0u : 0x80000000u;
            const float nf0f = __uint_as_float((__float_as_uint(ak0 * inv) & m0) ^ fs);
            const float nf1f = __uint_as_float((__float_as_uint(ak1 * inv) & m1) ^ fs);
            const u64 nf0 = pack2(nf0f, nf0f);
            const u64 nf1 = pack2(nf1f, nf1f);

            if (k < 31) {
                const int q4 = k >> 1;
                #pragma unroll
                for (int q = q4; q < 16; ++q) {
                    const u64 tq = sl ? A1[q] : A0[q];   // on lane p: pivot row
                    const u64 b  = __shfl_sync(FULLMASK, tq, p);
                    A0[q] = ffma2(b, nf0, A0[q]);
                    A1[q] = ffma2(b, nf1, A1[q]);
                }
            }
        }

        // ---- permutation parity: rows (t, t+16) pivoted at steps (ka, kb) ---
        // inversions of pi(orig_row)=step, counted once per unordered pair
        const unsigned pk16 = (unsigned)ka | ((unsigned)kb << 5);
        int inv = (ka > kb);                           // intra-lane pair
        #pragma unroll
        for (int sh = 1; sh < 16; ++sh) {
            const unsigned o = __shfl_sync(FULLMASK, pk16,
                                           (h << 4) | ((t + sh) & 15));
            const int tp  = (t + sh) & 15;
            const int kap = (int)(o & 31u);
            const int kbp = (int)(o >> 5);
            if (t < tp)
                inv += (ka > kap) + (ka > kbp) + (kap > kb) + (kb > kbp);
        }
        const unsigned bal = __ballot_sync(FULLMASK, inv & 1);
        const int par = __popc(bal & hm) & 1;

        // ---- det = sign * product of per-lane pivot products -----------------
        #pragma unroll
        for (int d = 1; d < 16; d <<= 1)
            det_local *= __shfl_xor_sync(FULLMASK, det_local, d);

        if (t == 0) out[s] = par ? -det_local : det_local;
    }
}

extern "C" void kernel_launch(void* const* d_in, const int* in_sizes, int n_in,
                              void* d_out, int out_size)
{
    const int4*  nvec = (const int4*)d_in[0];   // n: [131072, 128] int32
    const float* Phi  = (const float*)d_in[1];  // Phi: [32, 128] fp32
    float* out = (float*)d_out;                 // [131072] fp32
    slater_det_kernel<<<NBLOCKS, THREADS>>>(nvec, Phi, out);
}